// round 3
// baseline (speedup 1.0000x reference)
#include <cuda_runtime.h>

// Problem constants (fixed by the dataset)
#define NN 100000
#define EE 1600000

// Scratch: __device__ globals (no allocation allowed in kernel_launch).
// NOTE: these symbols must ONLY be referenced from device code. Passing them
// as kernel arguments from host code silently binds the HOST shadow address
// (dereferenceable on GB300 via ATS!) -> lost updates. That was the R2 bug.
__device__ int   g_is64;
__device__ int   g_src[EE];
__device__ int   g_dst[EE];
__device__ float g_t1[NN * 32];   // h0 @ W1_rel  (gathered per edge)
__device__ float g_a1[NN * 32];   // accumulator: h0 @ W1_root + b1 (+ edge adds)
__device__ float g_t2[NN * 48];
__device__ float g_a2[NN * 48];
__device__ float g_t3[NN * 16];

__device__ __forceinline__ void red4(float* p, float4 v) {
    asm volatile("red.global.add.v4.f32 [%0], {%1, %2, %3, %4};"
                 :: "l"(p), "f"(v.x), "f"(v.y), "f"(v.z), "f"(v.w)
                 : "memory");
}

// ---------------------------------------------------------------------------
// K-1: detect whether edge_index is int64 or int32.
// If the buffer is int32, interpreting it as int64 packs two random indices
// per value -> almost surely out of [0, N). If int64, all values are in range.
// ---------------------------------------------------------------------------
__global__ void k_detect(const void* __restrict__ ei, int N) {
    if (threadIdx.x == 0 && blockIdx.x == 0) {
        const long long* p = (const long long*)ei;
        int ok = 1;
        for (int i = 0; i < 64; i++) {
            long long v = p[i];
            if (v < 0 || v >= (long long)N) { ok = 0; break; }
        }
        g_is64 = ok;
    }
}

// ---------------------------------------------------------------------------
// K0: edge index -> int32 split arrays (dtype-agnostic)
// ---------------------------------------------------------------------------
__global__ __launch_bounds__(256) void k_idx(const void* __restrict__ ei, int E) {
    int i = blockIdx.x * blockDim.x + threadIdx.x;
    if (i >= E) return;
    if (g_is64) {
        const long long* p = (const long long*)ei;
        g_src[i] = (int)p[i];
        g_dst[i] = (int)p[E + i];
    } else {
        const int* p = (const int*)ei;
        g_src[i] = p[i];
        g_dst[i] = p[E + i];
    }
}

// ---------------------------------------------------------------------------
// K1: node kernel, layer 1.  h0 = concat(x[48], add_x[16]) -> 64
//     t1 = h0 @ W1_rel   a1 = h0 @ W1_root + b1
// ---------------------------------------------------------------------------
__global__ __launch_bounds__(256) void k_node1(
    const float* __restrict__ x, const float* __restrict__ ax,
    const float* __restrict__ Wrel, const float* __restrict__ Wroot,
    const float* __restrict__ b, int N)
{
    __shared__ float sWr[64 * 32];
    __shared__ float sWo[64 * 32];
    __shared__ float sb[32];
    for (int t = threadIdx.x; t < 64 * 32; t += 256) { sWr[t] = Wrel[t]; sWo[t] = Wroot[t]; }
    if (threadIdx.x < 32) sb[threadIdx.x] = b[threadIdx.x];
    __syncthreads();

    int i = blockIdx.x * 256 + threadIdx.x;
    if (i >= N) return;

    float h[64];
    const float4* xp = (const float4*)(x + (size_t)i * 48);
#pragma unroll
    for (int q = 0; q < 12; q++) {
        float4 v = xp[q];
        h[4*q] = v.x; h[4*q+1] = v.y; h[4*q+2] = v.z; h[4*q+3] = v.w;
    }
    const float4* ap = (const float4*)(ax + (size_t)i * 16);
#pragma unroll
    for (int q = 0; q < 4; q++) {
        float4 v = ap[q];
        h[48+4*q] = v.x; h[48+4*q+1] = v.y; h[48+4*q+2] = v.z; h[48+4*q+3] = v.w;
    }

    float* t1 = g_t1 + (size_t)i * 32;
    float* a1 = g_a1 + (size_t)i * 32;
#pragma unroll 4
    for (int j = 0; j < 32; j++) {
        float st = 0.0f;
        float sr = sb[j];
#pragma unroll
        for (int k = 0; k < 64; k++) {
            st = fmaf(h[k], sWr[k * 32 + j], st);
            sr = fmaf(h[k], sWo[k * 32 + j], sr);
        }
        t1[j] = st;
        a1[j] = sr;
    }
}

// ---------------------------------------------------------------------------
// K3: node kernel, layer 2.  h1 = concat(relu(a1)[32], lf[16]) -> 48
//     t2 = h1 @ W2_rel   a2 = h1 @ W2_root + b2
// ---------------------------------------------------------------------------
__global__ __launch_bounds__(256) void k_node2(
    const float* __restrict__ lf,
    const float* __restrict__ Wrel, const float* __restrict__ Wroot,
    const float* __restrict__ b, int N)
{
    __shared__ float sWr[48 * 48];
    __shared__ float sWo[48 * 48];
    __shared__ float sb[48];
    for (int t = threadIdx.x; t < 48 * 48; t += 256) { sWr[t] = Wrel[t]; sWo[t] = Wroot[t]; }
    if (threadIdx.x < 48) sb[threadIdx.x] = b[threadIdx.x];
    __syncthreads();

    int i = blockIdx.x * 256 + threadIdx.x;
    if (i >= N) return;

    float h[48];
    const float4* a1p = (const float4*)(g_a1 + (size_t)i * 32);
#pragma unroll
    for (int q = 0; q < 8; q++) {
        float4 v = a1p[q];
        h[4*q]   = fmaxf(v.x, 0.0f);
        h[4*q+1] = fmaxf(v.y, 0.0f);
        h[4*q+2] = fmaxf(v.z, 0.0f);
        h[4*q+3] = fmaxf(v.w, 0.0f);
    }
    const float4* lp = (const float4*)(lf + (size_t)i * 16);
#pragma unroll
    for (int q = 0; q < 4; q++) {
        float4 v = lp[q];
        h[32+4*q] = v.x; h[32+4*q+1] = v.y; h[32+4*q+2] = v.z; h[32+4*q+3] = v.w;
    }

    float* t2 = g_t2 + (size_t)i * 48;
    float* a2 = g_a2 + (size_t)i * 48;
#pragma unroll 4
    for (int j = 0; j < 48; j++) {
        float st = 0.0f;
        float sr = sb[j];
#pragma unroll
        for (int k = 0; k < 48; k++) {
            st = fmaf(h[k], sWr[k * 48 + j], st);
            sr = fmaf(h[k], sWo[k * 48 + j], sr);
        }
        t2[j] = st;
        a2[j] = sr;
    }
}

// ---------------------------------------------------------------------------
// K5: node kernel, layer 3.  h2 = relu(a2)[48]
//     t3 = h2 @ W3_rel   out_init = h2 @ W3_root + b3 + add_x
// ---------------------------------------------------------------------------
__global__ __launch_bounds__(256) void k_node3(
    const float* __restrict__ ax,
    const float* __restrict__ Wrel, const float* __restrict__ Wroot,
    const float* __restrict__ b, float* __restrict__ out, int N)
{
    __shared__ float sWr[48 * 16];
    __shared__ float sWo[48 * 16];
    __shared__ float sb[16];
    for (int t = threadIdx.x; t < 48 * 16; t += 256) { sWr[t] = Wrel[t]; sWo[t] = Wroot[t]; }
    if (threadIdx.x < 16) sb[threadIdx.x] = b[threadIdx.x];
    __syncthreads();

    int i = blockIdx.x * 256 + threadIdx.x;
    if (i >= N) return;

    float h[48];
    const float4* a2p = (const float4*)(g_a2 + (size_t)i * 48);
#pragma unroll
    for (int q = 0; q < 12; q++) {
        float4 v = a2p[q];
        h[4*q]   = fmaxf(v.x, 0.0f);
        h[4*q+1] = fmaxf(v.y, 0.0f);
        h[4*q+2] = fmaxf(v.z, 0.0f);
        h[4*q+3] = fmaxf(v.w, 0.0f);
    }

    const float* axr = ax + (size_t)i * 16;
    float* t3 = g_t3 + (size_t)i * 16;
    float* o  = out + (size_t)i * 16;
#pragma unroll 4
    for (int j = 0; j < 16; j++) {
        float st = 0.0f;
        float sr = sb[j] + axr[j];
#pragma unroll
        for (int k = 0; k < 48; k++) {
            st = fmaf(h[k], sWr[k * 16 + j], st);
            sr = fmaf(h[k], sWo[k * 16 + j], sr);
        }
        t3[j] = st;
        o[j]  = sr;
    }
}

// ---------------------------------------------------------------------------
// Edge scatter core: acc[dst] += t[src], CH float4 chunks per edge.
// t/acc are resolved in DEVICE code only (see R2 post-mortem).
// ---------------------------------------------------------------------------
template <int CH>
__device__ __forceinline__ void edge_body(
    const float* __restrict__ t, float* __restrict__ acc, int E)
{
    int tid = blockIdx.x * blockDim.x + threadIdx.x;
    if (tid >= E * CH) return;
    int e = tid / CH;
    int c = tid - e * CH;
    int s = g_src[e];
    int d = g_dst[e];
    float4 v = *(const float4*)(t + (size_t)s * (CH * 4) + c * 4);
    red4(acc + (size_t)d * (CH * 4) + c * 4, v);
}

__global__ __launch_bounds__(256) void k_edge1(int E) { edge_body<8> (g_t1, g_a1, E); }
__global__ __launch_bounds__(256) void k_edge2(int E) { edge_body<12>(g_t2, g_a2, E); }
__global__ __launch_bounds__(256) void k_edge3(float* __restrict__ out, int E) {
    edge_body<4>(g_t3, out, E);
}

// ---------------------------------------------------------------------------
// kernel_launch
// ---------------------------------------------------------------------------
extern "C" void kernel_launch(void* const* d_in, const int* in_sizes, int n_in,
                              void* d_out, int out_size)
{
    const float* x   = (const float*)d_in[0];
    const void*  ei  = d_in[1];
    const float* ax  = (const float*)d_in[2];
    const float* lf  = (const float*)d_in[3];
    const float* W1r = (const float*)d_in[4];
    const float* b1  = (const float*)d_in[5];
    const float* W1o = (const float*)d_in[6];
    const float* W2r = (const float*)d_in[7];
    const float* b2  = (const float*)d_in[8];
    const float* W2o = (const float*)d_in[9];
    const float* W3r = (const float*)d_in[10];
    const float* b3  = (const float*)d_in[11];
    const float* W3o = (const float*)d_in[12];
    float* out = (float*)d_out;

    const int N = in_sizes[0] / 48;
    const int E = in_sizes[1] / 2;

    const int TB = 256;
    const int nodeBlocks = (N + TB - 1) / TB;

    k_detect<<<1, 32>>>(ei, N);
    k_idx<<<(E + TB - 1) / TB, TB>>>(ei, E);

    // Layer 1 (width 32 -> 8 float4 chunks/edge)
    k_node1<<<nodeBlocks, TB>>>(x, ax, W1r, W1o, b1, N);
    k_edge1<<<((long long)E * 8 + TB - 1) / TB, TB>>>(E);

    // Layer 2 (width 48 -> 12 chunks/edge)
    k_node2<<<nodeBlocks, TB>>>(lf, W2r, W2o, b2, N);
    k_edge2<<<((long long)E * 12 + TB - 1) / TB, TB>>>(E);

    // Layer 3 (width 16 -> 4 chunks/edge), accumulate straight into d_out
    k_node3<<<nodeBlocks, TB>>>(ax, W3r, W3o, b3, out, N);
    k_edge3<<<((long long)E * 4 + TB - 1) / TB, TB>>>(out, E);
}

// round 4
// speedup vs baseline: 1.8771x; 1.8771x over previous
#include <cuda_runtime.h>

// Problem constants (fixed by the dataset)
#define NN 100000
#define EE 1600000

// Scratch: __device__ globals (no allocation allowed in kernel_launch).
// NOTE: only referenced from device code — passing them as kernel args from
// host binds the HOST shadow (ATS-dereferenceable on GB300!) -> R2 bug.
__device__ int   g_is64;
__device__ int   g_src[EE];
__device__ int   g_dst[EE];
__device__ float g_t1[NN * 32];
__device__ float g_a1[NN * 32];
__device__ float g_t2[NN * 48];
__device__ float g_a2[NN * 48];
__device__ float g_t3[NN * 16];

__device__ __forceinline__ void red4(float* p, float4 v) {
    asm volatile("red.global.add.v4.f32 [%0], {%1, %2, %3, %4};"
                 :: "l"(p), "f"(v.x), "f"(v.y), "f"(v.z), "f"(v.w)
                 : "memory");
}

// ---------------------------------------------------------------------------
// dtype probe: int32 read as int64 packs two random indices -> out of range
// ---------------------------------------------------------------------------
__global__ void k_detect(const void* __restrict__ ei, int N) {
    if (threadIdx.x == 0 && blockIdx.x == 0) {
        const long long* p = (const long long*)ei;
        int ok = 1;
        for (int i = 0; i < 64; i++) {
            long long v = p[i];
            if (v < 0 || v >= (long long)N) { ok = 0; break; }
        }
        g_is64 = ok;
    }
}

__global__ __launch_bounds__(256) void k_idx(const void* __restrict__ ei, int E) {
    int i = blockIdx.x * blockDim.x + threadIdx.x;
    if (i >= E) return;
    if (g_is64) {
        const long long* p = (const long long*)ei;
        g_src[i] = (int)p[i];
        g_dst[i] = (int)p[E + i];
    } else {
        const int* p = (const int*)ei;
        g_src[i] = p[i];
        g_dst[i] = p[E + i];
    }
}

// ---------------------------------------------------------------------------
// Dual-GEMM j-tile macro body: for 8 outputs, accumulate both matrices with
// ld.shared.v4 weight loads. h[] in registers, weights broadcast from smem.
// ---------------------------------------------------------------------------
#define JTILE_BODY(IN, OUT)                                                    \
    float at[8], ar[8];                                                        \
    _Pragma("unroll")                                                          \
    for (int u = 0; u < 8; u++) { at[u] = 0.0f; ar[u] = sb[jt + u]; }          \
    _Pragma("unroll")                                                          \
    for (int k = 0; k < IN; k++) {                                             \
        float hk = h[k];                                                       \
        float4 wr0 = *(const float4*)&sWr[k * OUT + jt];                       \
        float4 wr1 = *(const float4*)&sWr[k * OUT + jt + 4];                   \
        float4 wo0 = *(const float4*)&sWo[k * OUT + jt];                       \
        float4 wo1 = *(const float4*)&sWo[k * OUT + jt + 4];                   \
        at[0] = fmaf(hk, wr0.x, at[0]); at[1] = fmaf(hk, wr0.y, at[1]);        \
        at[2] = fmaf(hk, wr0.z, at[2]); at[3] = fmaf(hk, wr0.w, at[3]);        \
        at[4] = fmaf(hk, wr1.x, at[4]); at[5] = fmaf(hk, wr1.y, at[5]);        \
        at[6] = fmaf(hk, wr1.z, at[6]); at[7] = fmaf(hk, wr1.w, at[7]);        \
        ar[0] = fmaf(hk, wo0.x, ar[0]); ar[1] = fmaf(hk, wo0.y, ar[1]);        \
        ar[2] = fmaf(hk, wo0.z, ar[2]); ar[3] = fmaf(hk, wo0.w, ar[3]);        \
        ar[4] = fmaf(hk, wo1.x, ar[4]); ar[5] = fmaf(hk, wo1.y, ar[5]);        \
        ar[6] = fmaf(hk, wo1.z, ar[6]); ar[7] = fmaf(hk, wo1.w, ar[7]);        \
    }

// ---------------------------------------------------------------------------
// K1: layer 1 node kernel. h0 = concat(x[48], ax[16]) -> 64
//     t1 = h0 @ W1_rel ; a1 = h0 @ W1_root + b1
// ---------------------------------------------------------------------------
__global__ __launch_bounds__(256) void k_node1(
    const float* __restrict__ x, const float* __restrict__ ax,
    const float* __restrict__ Wrel, const float* __restrict__ Wroot,
    const float* __restrict__ b, int N)
{
    __shared__ __align__(16) float sWr[64 * 32];
    __shared__ __align__(16) float sWo[64 * 32];
    __shared__ float sb[32];
    for (int t = threadIdx.x; t < 64 * 32; t += 256) { sWr[t] = Wrel[t]; sWo[t] = Wroot[t]; }
    if (threadIdx.x < 32) sb[threadIdx.x] = b[threadIdx.x];
    __syncthreads();

    int i = blockIdx.x * 256 + threadIdx.x;
    if (i >= N) return;

    float h[64];
    const float4* xp = (const float4*)(x + (size_t)i * 48);
#pragma unroll
    for (int q = 0; q < 12; q++) {
        float4 v = xp[q];
        h[4*q] = v.x; h[4*q+1] = v.y; h[4*q+2] = v.z; h[4*q+3] = v.w;
    }
    const float4* ap = (const float4*)(ax + (size_t)i * 16);
#pragma unroll
    for (int q = 0; q < 4; q++) {
        float4 v = ap[q];
        h[48+4*q] = v.x; h[48+4*q+1] = v.y; h[48+4*q+2] = v.z; h[48+4*q+3] = v.w;
    }

    float* t1 = g_t1 + (size_t)i * 32;
    float* a1 = g_a1 + (size_t)i * 32;
#pragma unroll 1
    for (int jt = 0; jt < 32; jt += 8) {
        JTILE_BODY(64, 32)
        *(float4*)&t1[jt]     = make_float4(at[0], at[1], at[2], at[3]);
        *(float4*)&t1[jt + 4] = make_float4(at[4], at[5], at[6], at[7]);
        *(float4*)&a1[jt]     = make_float4(ar[0], ar[1], ar[2], ar[3]);
        *(float4*)&a1[jt + 4] = make_float4(ar[4], ar[5], ar[6], ar[7]);
    }
}

// ---------------------------------------------------------------------------
// K3: layer 2 node kernel. h1 = concat(relu(a1)[32], lf[16]) -> 48
// ---------------------------------------------------------------------------
__global__ __launch_bounds__(256) void k_node2(
    const float* __restrict__ lf,
    const float* __restrict__ Wrel, const float* __restrict__ Wroot,
    const float* __restrict__ b, int N)
{
    __shared__ __align__(16) float sWr[48 * 48];
    __shared__ __align__(16) float sWo[48 * 48];
    __shared__ float sb[48];
    for (int t = threadIdx.x; t < 48 * 48; t += 256) { sWr[t] = Wrel[t]; sWo[t] = Wroot[t]; }
    if (threadIdx.x < 48) sb[threadIdx.x] = b[threadIdx.x];
    __syncthreads();

    int i = blockIdx.x * 256 + threadIdx.x;
    if (i >= N) return;

    float h[48];
    const float4* a1p = (const float4*)(g_a1 + (size_t)i * 32);
#pragma unroll
    for (int q = 0; q < 8; q++) {
        float4 v = a1p[q];
        h[4*q]   = fmaxf(v.x, 0.0f);
        h[4*q+1] = fmaxf(v.y, 0.0f);
        h[4*q+2] = fmaxf(v.z, 0.0f);
        h[4*q+3] = fmaxf(v.w, 0.0f);
    }
    const float4* lp = (const float4*)(lf + (size_t)i * 16);
#pragma unroll
    for (int q = 0; q < 4; q++) {
        float4 v = lp[q];
        h[32+4*q] = v.x; h[32+4*q+1] = v.y; h[32+4*q+2] = v.z; h[32+4*q+3] = v.w;
    }

    float* t2 = g_t2 + (size_t)i * 48;
    float* a2 = g_a2 + (size_t)i * 48;
#pragma unroll 1
    for (int jt = 0; jt < 48; jt += 8) {
        JTILE_BODY(48, 48)
        *(float4*)&t2[jt]     = make_float4(at[0], at[1], at[2], at[3]);
        *(float4*)&t2[jt + 4] = make_float4(at[4], at[5], at[6], at[7]);
        *(float4*)&a2[jt]     = make_float4(ar[0], ar[1], ar[2], ar[3]);
        *(float4*)&a2[jt + 4] = make_float4(ar[4], ar[5], ar[6], ar[7]);
    }
}

// ---------------------------------------------------------------------------
// K5: layer 3 node kernel. h2 = relu(a2)[48]
//     t3 = h2 @ W3_rel ; out = h2 @ W3_root + b3 + ax
// ---------------------------------------------------------------------------
__global__ __launch_bounds__(256) void k_node3(
    const float* __restrict__ ax,
    const float* __restrict__ Wrel, const float* __restrict__ Wroot,
    const float* __restrict__ b, float* __restrict__ out, int N)
{
    __shared__ __align__(16) float sWr[48 * 16];
    __shared__ __align__(16) float sWo[48 * 16];
    __shared__ float sb[16];
    for (int t = threadIdx.x; t < 48 * 16; t += 256) { sWr[t] = Wrel[t]; sWo[t] = Wroot[t]; }
    if (threadIdx.x < 16) sb[threadIdx.x] = b[threadIdx.x];
    __syncthreads();

    int i = blockIdx.x * 256 + threadIdx.x;
    if (i >= N) return;

    float h[48];
    const float4* a2p = (const float4*)(g_a2 + (size_t)i * 48);
#pragma unroll
    for (int q = 0; q < 12; q++) {
        float4 v = a2p[q];
        h[4*q]   = fmaxf(v.x, 0.0f);
        h[4*q+1] = fmaxf(v.y, 0.0f);
        h[4*q+2] = fmaxf(v.z, 0.0f);
        h[4*q+3] = fmaxf(v.w, 0.0f);
    }

    const float4* axp = (const float4*)(ax + (size_t)i * 16);
    float* t3 = g_t3 + (size_t)i * 16;
    float* o  = out + (size_t)i * 16;
#pragma unroll 1
    for (int jt = 0; jt < 16; jt += 8) {
        JTILE_BODY(48, 16)
        float4 av0 = axp[jt / 4];
        float4 av1 = axp[jt / 4 + 1];
        *(float4*)&t3[jt]     = make_float4(at[0], at[1], at[2], at[3]);
        *(float4*)&t3[jt + 4] = make_float4(at[4], at[5], at[6], at[7]);
        *(float4*)&o[jt]      = make_float4(ar[0] + av0.x, ar[1] + av0.y,
                                            ar[2] + av0.z, ar[3] + av0.w);
        *(float4*)&o[jt + 4]  = make_float4(ar[4] + av1.x, ar[5] + av1.y,
                                            ar[6] + av1.z, ar[7] + av1.w);
    }
}

// ---------------------------------------------------------------------------
// Edge scatter: acc[dst] += t[src], CH float4 chunks per edge.
// Lane-adjacent threads cover consecutive chunks of one edge -> coalesced.
// ---------------------------------------------------------------------------
template <int CH>
__device__ __forceinline__ void edge_body(
    const float* __restrict__ t, float* __restrict__ acc, int E)
{
    int tid = blockIdx.x * blockDim.x + threadIdx.x;
    if (tid >= E * CH) return;
    int e = tid / CH;
    int c = tid - e * CH;
    int s = g_src[e];
    int d = g_dst[e];
    float4 v = *(const float4*)(t + (size_t)s * (CH * 4) + c * 4);
    red4(acc + (size_t)d * (CH * 4) + c * 4, v);
}

__global__ __launch_bounds__(256) void k_edge1(int E) { edge_body<8> (g_t1, g_a1, E); }
__global__ __launch_bounds__(256) void k_edge2(int E) { edge_body<12>(g_t2, g_a2, E); }
__global__ __launch_bounds__(256) void k_edge3(float* __restrict__ out, int E) {
    edge_body<4>(g_t3, out, E);
}

// ---------------------------------------------------------------------------
// kernel_launch
// ---------------------------------------------------------------------------
extern "C" void kernel_launch(void* const* d_in, const int* in_sizes, int n_in,
                              void* d_out, int out_size)
{
    const float* x   = (const float*)d_in[0];
    const void*  ei  = d_in[1];
    const float* ax  = (const float*)d_in[2];
    const float* lf  = (const float*)d_in[3];
    const float* W1r = (const float*)d_in[4];
    const float* b1  = (const float*)d_in[5];
    const float* W1o = (const float*)d_in[6];
    const float* W2r = (const float*)d_in[7];
    const float* b2  = (const float*)d_in[8];
    const float* W2o = (const float*)d_in[9];
    const float* W3r = (const float*)d_in[10];
    const float* b3  = (const float*)d_in[11];
    const float* W3o = (const float*)d_in[12];
    float* out = (float*)d_out;

    const int N = in_sizes[0] / 48;
    const int E = in_sizes[1] / 2;

    const int TB = 256;
    const int nodeBlocks = (N + TB - 1) / TB;

    k_detect<<<1, 32>>>(ei, N);
    k_idx<<<(E + TB - 1) / TB, TB>>>(ei, E);

    // Layer 1 (width 32 -> 8 float4 chunks/edge)
    k_node1<<<nodeBlocks, TB>>>(x, ax, W1r, W1o, b1, N);
    k_edge1<<<((long long)E * 8 + TB - 1) / TB, TB>>>(E);

    // Layer 2 (width 48 -> 12 chunks/edge)
    k_node2<<<nodeBlocks, TB>>>(lf, W2r, W2o, b2, N);
    k_edge2<<<((long long)E * 12 + TB - 1) / TB, TB>>>(E);

    // Layer 3 (width 16 -> 4 chunks/edge), accumulate straight into d_out
    k_node3<<<nodeBlocks, TB>>>(ax, W3r, W3o, b3, out, N);
    k_edge3<<<((long long)E * 4 + TB - 1) / TB, TB>>>(out, E);
}